// round 3
// baseline (speedup 1.0000x reference)
#include <cuda_runtime.h>
#include <cuda_bf16.h>

#define BATCH 4096
#define TT    512
#define IN    20
#define HID   51
#define NG    204   // 4*HID
#define SPB   8     // sequences per block
#define NBLK  (BATCH / SPB)   // 512 blocks

// ---- packed f32x2 helpers (sm_103a) ----
__device__ __forceinline__ unsigned long long pack2(float v) {
    unsigned long long r;
    asm("mov.b64 %0, {%1, %1};" : "=l"(r) : "f"(v));
    return r;
}
__device__ __forceinline__ unsigned long long fma2(unsigned long long a,
                                                   unsigned long long b,
                                                   unsigned long long c) {
    unsigned long long d;
    asm("fma.rn.f32x2 %0, %1, %2, %3;" : "=l"(d) : "l"(a), "l"(b), "l"(c));
    return d;
}

// ---- fast activations: MUFU ex2 + rcp, rel err ~1e-6 (plenty vs 1e-3 tol) ----
__device__ __forceinline__ float fsig(float x)  { return __fdividef(1.0f, 1.0f + __expf(-x)); }
__device__ __forceinline__ float ftanh_(float x){ return 1.0f - __fdividef(2.0f, __expf(2.0f * x) + 1.0f); }

__global__ __launch_bounds__(256, 1) void lstm8_kernel(
    const float* __restrict__ x,
    const float* __restrict__ W_ih1, const float* __restrict__ W_hh1,
    const float* __restrict__ b_ih1, const float* __restrict__ b_hh1,
    const float* __restrict__ W_ih2, const float* __restrict__ W_hh2,
    const float* __restrict__ b_ih2, const float* __restrict__ b_hh2,
    const float* __restrict__ W_mu,  const float* __restrict__ b_mu,
    const float* __restrict__ W_lv,  const float* __restrict__ b_lv,
    float* __restrict__ out)
{
    const int b8  = blockIdx.x * SPB;
    const int tid = threadIdx.x;

    // seq-packed layouts: [k][seq] so one LDS.128 = seqs 0..3 (= two f32x2 pairs)
    __shared__ __align__(16) float x_sh[2][IN][SPB];      // double-buffered input
    __shared__ __align__(16) float h_sh[HID][SPB];        // layer-1 hidden state
    __shared__ __align__(16) float gates_sh[NG][SPB];     // raw gate pre-activations
    __shared__ float w2_sh[NG];                           // W_ih2 transposed [u*4+g]

    // ---- per-thread layer-1 weights, packed {w,w} (142 regs) ----
    unsigned long long wxp[IN], whp[HID], biasp = 0ULL;
    if (tid < NG) {
        #pragma unroll
        for (int k = 0; k < IN;  k++) wxp[k] = pack2(W_ih1[tid * IN  + k]);
        #pragma unroll
        for (int k = 0; k < HID; k++) whp[k] = pack2(W_hh1[tid * HID + k]);
        biasp = pack2(b_ih1[tid] + b_hh1[tid]);
        w2_sh[tid] = W_ih2[(tid & 3) * HID + (tid >> 2)];
        int u = tid >> 2, s = tid & 3;
        h_sh[u][s] = 0.f; h_sh[u][s + 4] = 0.f;
    }
    float c1a = 0.f, c1b = 0.f;   // cell state for (s,u) and (s+4,u)

    // ---- warp 7: layer 2, lane = (s2, g2), pipelined one step behind ----
    const int lane = tid - 224;
    const int s2 = lane >> 2, g2 = lane & 3;
    float l2_bias = 0.f, l2_whh = 0.f;
    float c2 = 0.f, h2 = 0.f, sum_h2 = 0.f;
    if (tid >= 224) {
        l2_bias = b_ih2[g2] + b_hh2[g2];
        l2_whh  = W_hh2[g2];
    }

    // ---- preload x[t=0] into buffer 0 (threads 204..223) ----
    if (tid >= NG && tid < NG + IN) {
        int j = tid - NG;
        {
            int s = j / 5, c = j % 5;
            float4 v = *reinterpret_cast<const float4*>(
                &x[((size_t)(b8 + s) * TT + 0) * IN + 4 * c]);
            x_sh[0][4*c+0][s] = v.x; x_sh[0][4*c+1][s] = v.y;
            x_sh[0][4*c+2][s] = v.z; x_sh[0][4*c+3][s] = v.w;
        }
        {
            int j2 = j + IN; int s = j2 / 5, c = j2 % 5;
            float4 v = *reinterpret_cast<const float4*>(
                &x[((size_t)(b8 + s) * TT + 0) * IN + 4 * c]);
            x_sh[0][4*c+0][s] = v.x; x_sh[0][4*c+1][s] = v.y;
            x_sh[0][4*c+2][s] = v.z; x_sh[0][4*c+3][s] = v.w;
        }
    }
    __syncthreads();

    float4 xr0 = make_float4(0,0,0,0), xr1 = make_float4(0,0,0,0);

    #pragma unroll 1
    for (int t = 0; t < TT; t++) {
        // ============ phase 0 ============
        if (tid < NG) {
            // gate row `tid` for 8 sequences: 4 independent FFMA2 chains
            unsigned long long a0 = biasp, a1 = biasp, a2 = biasp, a3 = biasp;
            const int buf = t & 1;
            #pragma unroll
            for (int k = 0; k < IN; k++) {
                ulonglong2 p = *reinterpret_cast<const ulonglong2*>(&x_sh[buf][k][0]);
                ulonglong2 q = *reinterpret_cast<const ulonglong2*>(&x_sh[buf][k][4]);
                a0 = fma2(wxp[k], p.x, a0); a1 = fma2(wxp[k], p.y, a1);
                a2 = fma2(wxp[k], q.x, a2); a3 = fma2(wxp[k], q.y, a3);
            }
            #pragma unroll
            for (int k = 0; k < HID; k++) {
                ulonglong2 p = *reinterpret_cast<const ulonglong2*>(&h_sh[k][0]);
                ulonglong2 q = *reinterpret_cast<const ulonglong2*>(&h_sh[k][4]);
                a0 = fma2(whp[k], p.x, a0); a1 = fma2(whp[k], p.y, a1);
                a2 = fma2(whp[k], q.x, a2); a3 = fma2(whp[k], q.y, a3);
            }
            *reinterpret_cast<ulonglong2*>(&gates_sh[tid][0]) = make_ulonglong2(a0, a1);
            *reinterpret_cast<ulonglong2*>(&gates_sh[tid][4]) = make_ulonglong2(a2, a3);
        } else if (tid < NG + IN) {
            // x prefetch for t+1 into registers (latency hidden by phase 0)
            if (t + 1 < TT) {
                int j = tid - NG;
                int sa = j / 5,       ca = j % 5;
                int j2 = j + IN, sb = j2 / 5, cb = j2 % 5;
                xr0 = *reinterpret_cast<const float4*>(
                    &x[((size_t)(b8 + sa) * TT + t + 1) * IN + 4 * ca]);
                xr1 = *reinterpret_cast<const float4*>(
                    &x[((size_t)(b8 + sb) * TT + t + 1) * IN + 4 * cb]);
            }
        } else {
            // warp 7: layer 2 for step t-1, reading h_sh = h1[t-1]
            float acc0 = 0.f, acc1 = 0.f, acc2 = 0.f;
            #pragma unroll
            for (int u = 0; u < HID; u += 3) {
                acc0 += w2_sh[(u+0)*4 + g2] * h_sh[u+0][s2];
                acc1 += w2_sh[(u+1)*4 + g2] * h_sh[u+1][s2];
                acc2 += w2_sh[(u+2)*4 + g2] * h_sh[u+2][s2];
            }
            float p = acc0 + acc1 + acc2;
            float pf = __shfl_sync(0xffffffffu, p, (s2 << 2) | 1);
            float pg = __shfl_sync(0xffffffffu, p, (s2 << 2) | 2);
            float po = __shfl_sync(0xffffffffu, p, (s2 << 2) | 3);
            float bf = __shfl_sync(0xffffffffu, l2_bias, (s2 << 2) | 1);
            float bg = __shfl_sync(0xffffffffu, l2_bias, (s2 << 2) | 2);
            float bo = __shfl_sync(0xffffffffu, l2_bias, (s2 << 2) | 3);
            float wf = __shfl_sync(0xffffffffu, l2_whh, (s2 << 2) | 1);
            float wg = __shfl_sync(0xffffffffu, l2_whh, (s2 << 2) | 2);
            float wo = __shfl_sync(0xffffffffu, l2_whh, (s2 << 2) | 3);
            if (t > 0 && g2 == 0) {
                float i2 = fsig  (p  + l2_bias + l2_whh * h2);
                float f2 = fsig  (pf + bf + wf * h2);
                float g2v= ftanh_(pg + bg + wg * h2);
                float o2 = fsig  (po + bo + wo * h2);
                c2 = f2 * c2 + i2 * g2v;
                h2 = o2 * ftanh_(c2);
                sum_h2 += h2;
            }
        }
        __syncthreads();

        // ============ phase 1 ============
        if (tid < NG) {
            const int u = tid >> 2, s = tid & 3;
            {
                float gi = gates_sh[u][s];
                float gf = gates_sh[HID   + u][s];
                float gg = gates_sh[2*HID + u][s];
                float go = gates_sh[3*HID + u][s];
                c1a = fsig(gf) * c1a + fsig(gi) * ftanh_(gg);
                h_sh[u][s] = fsig(go) * ftanh_(c1a);
            }
            {
                const int sb = s + 4;
                float gi = gates_sh[u][sb];
                float gf = gates_sh[HID   + u][sb];
                float gg = gates_sh[2*HID + u][sb];
                float go = gates_sh[3*HID + u][sb];
                c1b = fsig(gf) * c1b + fsig(gi) * ftanh_(gg);
                h_sh[u][sb] = fsig(go) * ftanh_(c1b);
            }
        } else if (tid < NG + IN) {
            if (t + 1 < TT) {
                int j = tid - NG;
                int sa = j / 5,       ca = j % 5;
                int j2 = j + IN, sb = j2 / 5, cb = j2 % 5;
                const int nb = (t + 1) & 1;
                x_sh[nb][4*ca+0][sa] = xr0.x; x_sh[nb][4*ca+1][sa] = xr0.y;
                x_sh[nb][4*ca+2][sa] = xr0.z; x_sh[nb][4*ca+3][sa] = xr0.w;
                x_sh[nb][4*cb+0][sb] = xr1.x; x_sh[nb][4*cb+1][sb] = xr1.y;
                x_sh[nb][4*cb+2][sb] = xr1.z; x_sh[nb][4*cb+3][sb] = xr1.w;
            }
        }
        __syncthreads();
    }

    // ---- final layer-2 step (t = TT-1) + epilogue ----
    if (tid >= 224) {
        float acc0 = 0.f, acc1 = 0.f, acc2 = 0.f;
        #pragma unroll
        for (int u = 0; u < HID; u += 3) {
            acc0 += w2_sh[(u+0)*4 + g2] * h_sh[u+0][s2];
            acc1 += w2_sh[(u+1)*4 + g2] * h_sh[u+1][s2];
            acc2 += w2_sh[(u+2)*4 + g2] * h_sh[u+2][s2];
        }
        float p = acc0 + acc1 + acc2;
        float pf = __shfl_sync(0xffffffffu, p, (s2 << 2) | 1);
        float pg = __shfl_sync(0xffffffffu, p, (s2 << 2) | 2);
        float po = __shfl_sync(0xffffffffu, p, (s2 << 2) | 3);
        float bf = __shfl_sync(0xffffffffu, l2_bias, (s2 << 2) | 1);
        float bg = __shfl_sync(0xffffffffu, l2_bias, (s2 << 2) | 2);
        float bo = __shfl_sync(0xffffffffu, l2_bias, (s2 << 2) | 3);
        float wf = __shfl_sync(0xffffffffu, l2_whh, (s2 << 2) | 1);
        float wg = __shfl_sync(0xffffffffu, l2_whh, (s2 << 2) | 2);
        float wo = __shfl_sync(0xffffffffu, l2_whh, (s2 << 2) | 3);
        if (g2 == 0) {
            float i2 = fsig  (p  + l2_bias + l2_whh * h2);
            float f2 = fsig  (pf + bf + wf * h2);
            float g2v= ftanh_(pg + bg + wg * h2);
            float o2 = fsig  (po + bo + wo * h2);
            c2 = f2 * c2 + i2 * g2v;
            h2 = o2 * ftanh_(c2);
            sum_h2 += h2;

            // mean over T, heads, interval
            float agg = sum_h2 * (1.0f / TT);
            float mu  = W_mu[0] * agg + b_mu[0];
            float lv  = W_lv[0] * agg + b_lv[0];
            float sg  = __expf(0.5f * lv);
            int b = b8 + s2;
            out[b]             = mu - 1.96f * sg;
            out[BATCH + b]     = mu;
            out[2*BATCH + b]   = mu + 1.96f * sg;
            out[3*BATCH + b]   = lv;
        }
    }
}

extern "C" void kernel_launch(void* const* d_in, const int* in_sizes, int n_in,
                              void* d_out, int out_size) {
    const float* x     = (const float*)d_in[0];
    const float* W_ih1 = (const float*)d_in[1];
    const float* W_hh1 = (const float*)d_in[2];
    const float* b_ih1 = (const float*)d_in[3];
    const float* b_hh1 = (const float*)d_in[4];
    const float* W_ih2 = (const float*)d_in[5];
    const float* W_hh2 = (const float*)d_in[6];
    const float* b_ih2 = (const float*)d_in[7];
    const float* b_hh2 = (const float*)d_in[8];
    const float* W_mu  = (const float*)d_in[9];
    const float* b_mu  = (const float*)d_in[10];
    const float* W_lv  = (const float*)d_in[11];
    const float* b_lv  = (const float*)d_in[12];
    float* out = (float*)d_out;

    lstm8_kernel<<<NBLK, 256>>>(x, W_ih1, W_hh1, b_ih1, b_hh1,
                                W_ih2, W_hh2, b_ih2, b_hh2,
                                W_mu, b_mu, W_lv, b_lv, out);
}

// round 4
// speedup vs baseline: 1.7651x; 1.7651x over previous
#include <cuda_runtime.h>
#include <cuda_bf16.h>

#define BATCH 4096
#define TT    512
#define IN    20
#define HID   51
#define NG    204          // 4*HID
#define KDIM  71           // HID + IN
#define SPB   16           // sequences per block
#define NBLK  (BATCH / SPB)   // 256 blocks
#define NTHR  256

// float offsets inside dynamic smem
#define OFF_W   0                    // w_sh[71][204]  (transposed, [k][gate])
#define OFF_G   14484                // gates[204][20] (pitch 20 floats)
#define OFF_HX  (OFF_G + 204*20)     // hx[71][16]  rows 0..50 = h, 51..70 = x
#define OFF_B1  (OFF_HX + KDIM*16)   // combined layer-1 bias [204]
#define OFF_W2  (OFF_B1 + NG)        // W_ih2 [4*51]
#define SMEM_FLOATS (OFF_W2 + NG)
#define SMEM_BYTES  (SMEM_FLOATS * 4)

typedef unsigned long long ull;

__device__ __forceinline__ ull pack2(float v) {
    ull r; asm("mov.b64 %0, {%1, %1};" : "=l"(r) : "f"(v)); return r;
}
__device__ __forceinline__ ull fma2(ull a, ull b, ull c) {
    ull d; asm("fma.rn.f32x2 %0, %1, %2, %3;" : "=l"(d) : "l"(a), "l"(b), "l"(c)); return d;
}
__device__ __forceinline__ float fsig(float x)  { return __fdividef(1.0f, 1.0f + __expf(-x)); }
__device__ __forceinline__ float ftanh_(float x){ return 1.0f - __fdividef(2.0f, __expf(2.0f * x) + 1.0f); }

__global__ __launch_bounds__(NTHR, 2) void lstm_tile_kernel(
    const float* __restrict__ x,
    const float* __restrict__ W_ih1, const float* __restrict__ W_hh1,
    const float* __restrict__ b_ih1, const float* __restrict__ b_hh1,
    const float* __restrict__ W_ih2, const float* __restrict__ W_hh2,
    const float* __restrict__ b_ih2, const float* __restrict__ b_hh2,
    const float* __restrict__ W_mu,  const float* __restrict__ b_mu,
    const float* __restrict__ W_lv,  const float* __restrict__ b_lv,
    float* __restrict__ out)
{
    extern __shared__ float sm[];
    const int tid = threadIdx.x;
    const int b16 = blockIdx.x * SPB;

    // ---------- block init ----------
    // w_sh[k][g]: transposed weights; k<51 from W_hh1, k=51+j from W_ih1
    for (int i = tid; i < NG * HID; i += NTHR) {
        int g = i / HID, k = i % HID;
        sm[OFF_W + k * NG + g] = W_hh1[i];
    }
    for (int i = tid; i < NG * IN; i += NTHR) {
        int g = i / IN, j = i % IN;
        sm[OFF_W + (HID + j) * NG + g] = W_ih1[i];
    }
    if (tid < NG) {
        sm[OFF_B1 + tid] = b_ih1[tid] + b_hh1[tid];
        sm[OFF_W2 + tid] = W_ih2[tid];      // [4][51] row-major
        // zero h rows of hx (rows 0..50): 816 floats, 4 per thread
        #pragma unroll
        for (int j = 0; j < 4; j++) {
            int cell = tid + NG * j;        // 0..815
            sm[OFF_HX + cell] = 0.f;
        }
    }
    // x(t=0) into hx rows 51..70 (threads 204..219, one seq each)
    if (tid >= NG && tid < NG + SPB) {
        int s = tid - NG;
        const float4* xp = reinterpret_cast<const float4*>(
            &x[((size_t)(b16 + s) * TT) * IN]);
        #pragma unroll
        for (int q = 0; q < 5; q++) {
            float4 v = xp[q];
            sm[OFF_HX + (HID + 4*q + 0) * SPB + s] = v.x;
            sm[OFF_HX + (HID + 4*q + 1) * SPB + s] = v.y;
            sm[OFF_HX + (HID + 4*q + 2) * SPB + s] = v.z;
            sm[OFF_HX + (HID + 4*q + 3) * SPB + s] = v.w;
        }
    }

    // ---------- per-thread state ----------
    float c1[4] = {0.f, 0.f, 0.f, 0.f};                 // act threads (4 cells each)
    // layer-2 (warp 7, lanes 0..15 = seqs)
    const int l2s = tid - 224;
    float c2 = 0.f, h2 = 0.f, sum_h2 = 0.f;
    float l2b[4], l2w[4];
    if (tid >= 224 && l2s < SPB) {
        #pragma unroll
        for (int g = 0; g < 4; g++) { l2b[g] = b_ih2[g] + b_hh2[g]; l2w[g] = W_hh2[g]; }
    }

    const int g2 = tid >> 1;            // 0..101 -> gate rows 2*g2, 2*g2+1
    const int st = (tid & 1) << 3;      // seq sub-tile: 0 or 8

    __syncthreads();

    float4 xr[5];

    #pragma unroll 1
    for (int t = 0; t < TT; t++) {
        // =========== phase 0 ===========
        if (tid < NG) {
            // 2 gates x 8 seqs register tile; bias folded into accumulator init
            const ull bg0 = pack2(sm[OFF_B1 + 2*g2]);
            const ull bg1 = pack2(sm[OFF_B1 + 2*g2 + 1]);
            ull a0[4], a1[4];
            #pragma unroll
            for (int p = 0; p < 4; p++) { a0[p] = bg0; a1[p] = bg1; }
            const float* wrow = &sm[OFF_W + 2*g2];
            const float* hrow = &sm[OFF_HX + st];
            #pragma unroll
            for (int k = 0; k < KDIM; k++) {
                float2 wv = *reinterpret_cast<const float2*>(wrow + k * NG);
                ull w0 = pack2(wv.x), w1 = pack2(wv.y);
                ulonglong2 hA = *reinterpret_cast<const ulonglong2*>(hrow + k * SPB);
                ulonglong2 hB = *reinterpret_cast<const ulonglong2*>(hrow + k * SPB + 4);
                a0[0] = fma2(w0, hA.x, a0[0]); a0[1] = fma2(w0, hA.y, a0[1]);
                a0[2] = fma2(w0, hB.x, a0[2]); a0[3] = fma2(w0, hB.y, a0[3]);
                a1[0] = fma2(w1, hA.x, a1[0]); a1[1] = fma2(w1, hA.y, a1[1]);
                a1[2] = fma2(w1, hB.x, a1[2]); a1[3] = fma2(w1, hB.y, a1[3]);
            }
            float* gr0 = &sm[OFF_G + (2*g2)     * 20 + st];
            float* gr1 = &sm[OFF_G + (2*g2 + 1) * 20 + st];
            *reinterpret_cast<ulonglong2*>(gr0)     = make_ulonglong2(a0[0], a0[1]);
            *reinterpret_cast<ulonglong2*>(gr0 + 4) = make_ulonglong2(a0[2], a0[3]);
            *reinterpret_cast<ulonglong2*>(gr1)     = make_ulonglong2(a1[0], a1[1]);
            *reinterpret_cast<ulonglong2*>(gr1 + 4) = make_ulonglong2(a1[2], a1[3]);
        } else if (tid < NG + SPB) {
            // x prefetch for t+1
            if (t + 1 < TT) {
                int s = tid - NG;
                const float4* xp = reinterpret_cast<const float4*>(
                    &x[((size_t)(b16 + s) * TT + t + 1) * IN]);
                #pragma unroll
                for (int q = 0; q < 5; q++) xr[q] = xp[q];
            }
        } else if (tid >= 224 && l2s < SPB && t > 0) {
            // layer 2 consumes h(t-1) currently in hx
            float zi = 0.f, zf = 0.f, zg = 0.f, zo = 0.f;
            #pragma unroll
            for (int k = 0; k < HID; k++) {
                float hv = sm[OFF_HX + k * SPB + l2s];
                zi += sm[OFF_W2 +           k] * hv;
                zf += sm[OFF_W2 + HID     + k] * hv;
                zg += sm[OFF_W2 + 2*HID   + k] * hv;
                zo += sm[OFF_W2 + 3*HID   + k] * hv;
            }
            float i2 = fsig  (zi + l2b[0] + l2w[0] * h2);
            float f2 = fsig  (zf + l2b[1] + l2w[1] * h2);
            float g2v= ftanh_(zg + l2b[2] + l2w[2] * h2);
            float o2 = fsig  (zo + l2b[3] + l2w[3] * h2);
            c2 = f2 * c2 + i2 * g2v;
            h2 = o2 * ftanh_(c2);
            sum_h2 += h2;
        }
        __syncthreads();

        // =========== phase 1 ===========
        if (tid < NG) {
            #pragma unroll
            for (int j = 0; j < 4; j++) {
                int cell = tid + NG * j;         // 0..815
                int u = cell >> 4, s = cell & 15;
                float gi = sm[OFF_G + (u)        * 20 + s];
                float gf = sm[OFF_G + (HID + u)  * 20 + s];
                float gg = sm[OFF_G + (2*HID + u)* 20 + s];
                float go = sm[OFF_G + (3*HID + u)* 20 + s];
                float c  = fsig(gf) * c1[j] + fsig(gi) * ftanh_(gg);
                c1[j] = c;
                sm[OFF_HX + u * SPB + s] = fsig(go) * ftanh_(c);
            }
        } else if (tid < NG + SPB) {
            if (t + 1 < TT) {
                int s = tid - NG;
                #pragma unroll
                for (int q = 0; q < 5; q++) {
                    sm[OFF_HX + (HID + 4*q + 0) * SPB + s] = xr[q].x;
                    sm[OFF_HX + (HID + 4*q + 1) * SPB + s] = xr[q].y;
                    sm[OFF_HX + (HID + 4*q + 2) * SPB + s] = xr[q].z;
                    sm[OFF_HX + (HID + 4*q + 3) * SPB + s] = xr[q].w;
                }
            }
        }
        __syncthreads();
    }

    // ---------- final layer-2 step (h(T-1)) + epilogue ----------
    if (tid >= 224 && l2s < SPB) {
        float zi = 0.f, zf = 0.f, zg = 0.f, zo = 0.f;
        #pragma unroll
        for (int k = 0; k < HID; k++) {
            float hv = sm[OFF_HX + k * SPB + l2s];
            zi += sm[OFF_W2 +         k] * hv;
            zf += sm[OFF_W2 + HID   + k] * hv;
            zg += sm[OFF_W2 + 2*HID + k] * hv;
            zo += sm[OFF_W2 + 3*HID + k] * hv;
        }
        float i2 = fsig  (zi + l2b[0] + l2w[0] * h2);
        float f2 = fsig  (zf + l2b[1] + l2w[1] * h2);
        float g2v= ftanh_(zg + l2b[2] + l2w[2] * h2);
        float o2 = fsig  (zo + l2b[3] + l2w[3] * h2);
        c2 = f2 * c2 + i2 * g2v;
        h2 = o2 * ftanh_(c2);
        sum_h2 += h2;

        float agg = sum_h2 * (1.0f / TT);
        float mu  = W_mu[0] * agg + b_mu[0];
        float lv  = W_lv[0] * agg + b_lv[0];
        float sg  = __expf(0.5f * lv);
        int b = b16 + l2s;
        out[b]             = mu - 1.96f * sg;
        out[BATCH + b]     = mu;
        out[2*BATCH + b]   = mu + 1.96f * sg;
        out[3*BATCH + b]   = lv;
    }
}

extern "C" void kernel_launch(void* const* d_in, const int* in_sizes, int n_in,
                              void* d_out, int out_size) {
    const float* x     = (const float*)d_in[0];
    const float* W_ih1 = (const float*)d_in[1];
    const float* W_hh1 = (const float*)d_in[2];
    const float* b_ih1 = (const float*)d_in[3];
    const float* b_hh1 = (const float*)d_in[4];
    const float* W_ih2 = (const float*)d_in[5];
    const float* W_hh2 = (const float*)d_in[6];
    const float* b_ih2 = (const float*)d_in[7];
    const float* b_hh2 = (const float*)d_in[8];
    const float* W_mu  = (const float*)d_in[9];
    const float* b_mu  = (const float*)d_in[10];
    const float* W_lv  = (const float*)d_in[11];
    const float* b_lv  = (const float*)d_in[12];
    float* out = (float*)d_out;

    cudaFuncSetAttribute(lstm_tile_kernel,
                         cudaFuncAttributeMaxDynamicSharedMemorySize, SMEM_BYTES);
    lstm_tile_kernel<<<NBLK, NTHR, SMEM_BYTES>>>(x, W_ih1, W_hh1, b_ih1, b_hh1,
                                                 W_ih2, W_hh2, b_ih2, b_hh2,
                                                 W_mu, b_mu, W_lv, b_lv, out);
}

// round 5
// speedup vs baseline: 1.7656x; 1.0003x over previous
#include <cuda_runtime.h>
#include <cuda_bf16.h>

#define BATCH 4096
#define TT    512
#define IN    20
#define HID   51
#define NG    204          // 4*HID
#define KDIM  71           // HID + IN
#define SPB   16           // sequences per block
#define NBLK  (BATCH / SPB)   // 256 blocks
#define NTHR  256

// float offsets inside dynamic smem
#define OFF_W   0                    // w_sh[71][204]  (transposed, [k][gate])
#define OFF_G   14484                // gates[204][20] (pitch 20 floats)
#define OFF_HX  (OFF_G + 204*20)     // hx[71][16]  rows 0..50 = h, 51..70 = x
#define OFF_B1  (OFF_HX + KDIM*16)   // combined layer-1 bias [204]
#define OFF_W2  (OFF_B1 + NG)        // W_ih2 [4*51]
#define SMEM_FLOATS (OFF_W2 + NG)
#define SMEM_BYTES  (SMEM_FLOATS * 4)

typedef unsigned long long ull;

__device__ __forceinline__ ull pack2(float v) {
    ull r; asm("mov.b64 %0, {%1, %1};" : "=l"(r) : "f"(v)); return r;
}
__device__ __forceinline__ ull fma2(ull a, ull b, ull c) {
    ull d; asm("fma.rn.f32x2 %0, %1, %2, %3;" : "=l"(d) : "l"(a), "l"(b), "l"(c)); return d;
}
__device__ __forceinline__ float fsig(float x)  { return __fdividef(1.0f, 1.0f + __expf(-x)); }
__device__ __forceinline__ float ftanh_(float x){ return 1.0f - __fdividef(2.0f, __expf(2.0f * x) + 1.0f); }

__global__ __launch_bounds__(NTHR, 2) void lstm_tile_kernel(
    const float* __restrict__ x,
    const float* __restrict__ W_ih1, const float* __restrict__ W_hh1,
    const float* __restrict__ b_ih1, const float* __restrict__ b_hh1,
    const float* __restrict__ W_ih2, const float* __restrict__ W_hh2,
    const float* __restrict__ b_ih2, const float* __restrict__ b_hh2,
    const float* __restrict__ W_mu,  const float* __restrict__ b_mu,
    const float* __restrict__ W_lv,  const float* __restrict__ b_lv,
    float* __restrict__ out)
{
    extern __shared__ float sm[];
    const int tid = threadIdx.x;
    const int b16 = blockIdx.x * SPB;

    // ---------- block init ----------
    // w_sh[k][g]: transposed weights; k<51 from W_hh1, k=51+j from W_ih1
    for (int i = tid; i < NG * HID; i += NTHR) {
        int g = i / HID, k = i % HID;
        sm[OFF_W + k * NG + g] = W_hh1[i];
    }
    for (int i = tid; i < NG * IN; i += NTHR) {
        int g = i / IN, j = i % IN;
        sm[OFF_W + (HID + j) * NG + g] = W_ih1[i];
    }
    if (tid < NG) {
        sm[OFF_B1 + tid] = b_ih1[tid] + b_hh1[tid];
        sm[OFF_W2 + tid] = W_ih2[tid];      // [4][51] row-major
        // zero h rows of hx (rows 0..50): 816 floats, 4 per thread
        #pragma unroll
        for (int j = 0; j < 4; j++) {
            int cell = tid + NG * j;        // 0..815
            sm[OFF_HX + cell] = 0.f;
        }
    }
    // x(t=0) into hx rows 51..70 (threads 204..219, one seq each)
    if (tid >= NG && tid < NG + SPB) {
        int s = tid - NG;
        const float4* xp = reinterpret_cast<const float4*>(
            &x[((size_t)(b16 + s) * TT) * IN]);
        #pragma unroll
        for (int q = 0; q < 5; q++) {
            float4 v = xp[q];
            sm[OFF_HX + (HID + 4*q + 0) * SPB + s] = v.x;
            sm[OFF_HX + (HID + 4*q + 1) * SPB + s] = v.y;
            sm[OFF_HX + (HID + 4*q + 2) * SPB + s] = v.z;
            sm[OFF_HX + (HID + 4*q + 3) * SPB + s] = v.w;
        }
    }

    // ---------- per-thread state ----------
    float c1[4] = {0.f, 0.f, 0.f, 0.f};                 // act threads (4 cells each)
    // layer-2 (warp 7, lanes 0..15 = seqs)
    const int l2s = tid - 224;
    float c2 = 0.f, h2 = 0.f, sum_h2 = 0.f;
    float l2b[4], l2w[4];
    if (tid >= 224 && l2s < SPB) {
        #pragma unroll
        for (int g = 0; g < 4; g++) { l2b[g] = b_ih2[g] + b_hh2[g]; l2w[g] = W_hh2[g]; }
    }

    const int g2 = tid >> 1;            // 0..101 -> gate rows 2*g2, 2*g2+1
    const int st = (tid & 1) << 3;      // seq sub-tile: 0 or 8

    __syncthreads();

    float4 xr[5];

    #pragma unroll 1
    for (int t = 0; t < TT; t++) {
        // =========== phase 0 ===========
        if (tid < NG) {
            // 2 gates x 8 seqs register tile; bias folded into accumulator init
            const ull bg0 = pack2(sm[OFF_B1 + 2*g2]);
            const ull bg1 = pack2(sm[OFF_B1 + 2*g2 + 1]);
            ull a0[4], a1[4];
            #pragma unroll
            for (int p = 0; p < 4; p++) { a0[p] = bg0; a1[p] = bg1; }
            const float* wrow = &sm[OFF_W + 2*g2];
            const float* hrow = &sm[OFF_HX + st];
            #pragma unroll
            for (int k = 0; k < KDIM; k++) {
                float2 wv = *reinterpret_cast<const float2*>(wrow + k * NG);
                ull w0 = pack2(wv.x), w1 = pack2(wv.y);
                ulonglong2 hA = *reinterpret_cast<const ulonglong2*>(hrow + k * SPB);
                ulonglong2 hB = *reinterpret_cast<const ulonglong2*>(hrow + k * SPB + 4);
                a0[0] = fma2(w0, hA.x, a0[0]); a0[1] = fma2(w0, hA.y, a0[1]);
                a0[2] = fma2(w0, hB.x, a0[2]); a0[3] = fma2(w0, hB.y, a0[3]);
                a1[0] = fma2(w1, hA.x, a1[0]); a1[1] = fma2(w1, hA.y, a1[1]);
                a1[2] = fma2(w1, hB.x, a1[2]); a1[3] = fma2(w1, hB.y, a1[3]);
            }
            float* gr0 = &sm[OFF_G + (2*g2)     * 20 + st];
            float* gr1 = &sm[OFF_G + (2*g2 + 1) * 20 + st];
            *reinterpret_cast<ulonglong2*>(gr0)     = make_ulonglong2(a0[0], a0[1]);
            *reinterpret_cast<ulonglong2*>(gr0 + 4) = make_ulonglong2(a0[2], a0[3]);
            *reinterpret_cast<ulonglong2*>(gr1)     = make_ulonglong2(a1[0], a1[1]);
            *reinterpret_cast<ulonglong2*>(gr1 + 4) = make_ulonglong2(a1[2], a1[3]);
        } else if (tid < NG + SPB) {
            // x prefetch for t+1
            if (t + 1 < TT) {
                int s = tid - NG;
                const float4* xp = reinterpret_cast<const float4*>(
                    &x[((size_t)(b16 + s) * TT + t + 1) * IN]);
                #pragma unroll
                for (int q = 0; q < 5; q++) xr[q] = xp[q];
            }
        } else if (tid >= 224 && l2s < SPB && t > 0) {
            // layer 2 consumes h(t-1) currently in hx
            float zi = 0.f, zf = 0.f, zg = 0.f, zo = 0.f;
            #pragma unroll
            for (int k = 0; k < HID; k++) {
                float hv = sm[OFF_HX + k * SPB + l2s];
                zi += sm[OFF_W2 +           k] * hv;
                zf += sm[OFF_W2 + HID     + k] * hv;
                zg += sm[OFF_W2 + 2*HID   + k] * hv;
                zo += sm[OFF_W2 + 3*HID   + k] * hv;
            }
            float i2 = fsig  (zi + l2b[0] + l2w[0] * h2);
            float f2 = fsig  (zf + l2b[1] + l2w[1] * h2);
            float g2v= ftanh_(zg + l2b[2] + l2w[2] * h2);
            float o2 = fsig  (zo + l2b[3] + l2w[3] * h2);
            c2 = f2 * c2 + i2 * g2v;
            h2 = o2 * ftanh_(c2);
            sum_h2 += h2;
        }
        __syncthreads();

        // =========== phase 1 ===========
        if (tid < NG) {
            #pragma unroll
            for (int j = 0; j < 4; j++) {
                int cell = tid + NG * j;         // 0..815
                int u = cell >> 4, s = cell & 15;
                float gi = sm[OFF_G + (u)        * 20 + s];
                float gf = sm[OFF_G + (HID + u)  * 20 + s];
                float gg = sm[OFF_G + (2*HID + u)* 20 + s];
                float go = sm[OFF_G + (3*HID + u)* 20 + s];
                float c  = fsig(gf) * c1[j] + fsig(gi) * ftanh_(gg);
                c1[j] = c;
                sm[OFF_HX + u * SPB + s] = fsig(go) * ftanh_(c);
            }
        } else if (tid < NG + SPB) {
            if (t + 1 < TT) {
                int s = tid - NG;
                #pragma unroll
                for (int q = 0; q < 5; q++) {
                    sm[OFF_HX + (HID + 4*q + 0) * SPB + s] = xr[q].x;
                    sm[OFF_HX + (HID + 4*q + 1) * SPB + s] = xr[q].y;
                    sm[OFF_HX + (HID + 4*q + 2) * SPB + s] = xr[q].z;
                    sm[OFF_HX + (HID + 4*q + 3) * SPB + s] = xr[q].w;
                }
            }
        }
        __syncthreads();
    }

    // ---------- final layer-2 step (h(T-1)) + epilogue ----------
    if (tid >= 224 && l2s < SPB) {
        float zi = 0.f, zf = 0.f, zg = 0.f, zo = 0.f;
        #pragma unroll
        for (int k = 0; k < HID; k++) {
            float hv = sm[OFF_HX + k * SPB + l2s];
            zi += sm[OFF_W2 +         k] * hv;
            zf += sm[OFF_W2 + HID   + k] * hv;
            zg += sm[OFF_W2 + 2*HID + k] * hv;
            zo += sm[OFF_W2 + 3*HID + k] * hv;
        }
        float i2 = fsig  (zi + l2b[0] + l2w[0] * h2);
        float f2 = fsig  (zf + l2b[1] + l2w[1] * h2);
        float g2v= ftanh_(zg + l2b[2] + l2w[2] * h2);
        float o2 = fsig  (zo + l2b[3] + l2w[3] * h2);
        c2 = f2 * c2 + i2 * g2v;
        h2 = o2 * ftanh_(c2);
        sum_h2 += h2;

        float agg = sum_h2 * (1.0f / TT);
        float mu  = W_mu[0] * agg + b_mu[0];
        float lv  = W_lv[0] * agg + b_lv[0];
        float sg  = __expf(0.5f * lv);
        int b = b16 + l2s;
        out[b]             = mu - 1.96f * sg;
        out[BATCH + b]     = mu;
        out[2*BATCH + b]   = mu + 1.96f * sg;
        out[3*BATCH + b]   = lv;
    }
}

extern "C" void kernel_launch(void* const* d_in, const int* in_sizes, int n_in,
                              void* d_out, int out_size) {
    const float* x     = (const float*)d_in[0];
    const float* W_ih1 = (const float*)d_in[1];
    const float* W_hh1 = (const float*)d_in[2];
    const float* b_ih1 = (const float*)d_in[3];
    const float* b_hh1 = (const float*)d_in[4];
    const float* W_ih2 = (const float*)d_in[5];
    const float* W_hh2 = (const float*)d_in[6];
    const float* b_ih2 = (const float*)d_in[7];
    const float* b_hh2 = (const float*)d_in[8];
    const float* W_mu  = (const float*)d_in[9];
    const float* b_mu  = (const float*)d_in[10];
    const float* W_lv  = (const float*)d_in[11];
    const float* b_lv  = (const float*)d_in[12];
    float* out = (float*)d_out;

    cudaFuncSetAttribute(lstm_tile_kernel,
                         cudaFuncAttributeMaxDynamicSharedMemorySize, SMEM_BYTES);
    lstm_tile_kernel<<<NBLK, NTHR, SMEM_BYTES>>>(x, W_ih1, W_hh1, b_ih1, b_hh1,
                                                 W_ih2, W_hh2, b_ih2, b_hh2,
                                                 W_mu, b_mu, W_lv, b_lv, out);
}